// round 1
// baseline (speedup 1.0000x reference)
#include <cuda_runtime.h>

// Fused Poincare-ball: y = proj(expmap0(relu(logmap0(x))))
// Single pass: one float4 read + one float4 write per thread.
// 16 threads per row (D=64), per-row scalars via 16-lane xor-shuffle reduction.

#define MIN_NORM  1e-7f
#define BALL_EPS  4e-3f
#define ATANH_EPS 1e-7f

__global__ __launch_bounds__(256, 8)
void act_hyp_kernel(const float* __restrict__ x,
                    const float* __restrict__ c,
                    float* __restrict__ out,
                    int nrows)
{
    const int row  = blockIdx.x * 16 + (threadIdx.x >> 4);
    if (row >= nrows) return;
    const int lane = threadIdx.x & 15;

    const float4* xp = reinterpret_cast<const float4*>(x) + (size_t)row * 16 + lane;
    float4 v = *xp;

    // relu'd copy
    float r0 = fmaxf(v.x, 0.0f);
    float r1 = fmaxf(v.y, 0.0f);
    float r2 = fmaxf(v.z, 0.0f);
    float r3 = fmaxf(v.w, 0.0f);

    // partial sums: ||x||^2 and ||relu(x)||^2 in the same pass
    float s2  = v.x*v.x + v.y*v.y + v.z*v.z + v.w*v.w;
    float s2p = r0*r0 + r1*r1 + r2*r2 + r3*r3;

    // 16-lane xor reduction (groups of 16 are aligned within the warp)
    #pragma unroll
    for (int off = 8; off >= 1; off >>= 1) {
        s2  += __shfl_xor_sync(0xFFFFFFFFu, s2,  off);
        s2p += __shfl_xor_sync(0xFFFFFFFFu, s2p, off);
    }

    const float sqrt_c = sqrtf(c[0]);

    // logmap0 scale: f = atanh(min(sc*xn, 1-eps)) / (sc*xn), xn clamped
    float xn  = fmaxf(sqrtf(s2), MIN_NORM);
    float sxn = sqrt_c * xn;
    float arg = fminf(sxn, 1.0f - ATANH_EPS);
    float f   = atanhf(arg) / sxn;

    // expmap0 scale: t = tanh(sc*un) / (sc*un), un = f * ||relu(x)|| (clamped)
    float un  = fmaxf(f * sqrtf(s2p), MIN_NORM);
    float sun = sqrt_c * un;
    float t   = tanhf(sun) / sun;

    // proj: ||y|| = un * t (analytic; clamp matches reference since both >0)
    float yn      = fmaxf(un * t, MIN_NORM);
    float maxnorm = (1.0f - BALL_EPS) / sqrt_c;
    float ps      = (yn > maxnorm) ? (maxnorm / yn) : 1.0f;

    float m = f * t * ps;

    float4 o;
    o.x = r0 * m;
    o.y = r1 * m;
    o.z = r2 * m;
    o.w = r3 * m;
    reinterpret_cast<float4*>(out)[(size_t)row * 16 + lane] = o;
}

extern "C" void kernel_launch(void* const* d_in, const int* in_sizes, int n_in,
                              void* d_out, int out_size)
{
    const float* x = (const float*)d_in[0];
    const float* c = (const float*)d_in[1];
    float* out = (float*)d_out;

    int nrows = in_sizes[0] / 64;
    int blocks = (nrows + 15) / 16;   // 16 rows per 256-thread block
    act_hyp_kernel<<<blocks, 256>>>(x, c, out, nrows);
}

// round 2
// speedup vs baseline: 1.3996x; 1.3996x over previous
#include <cuda_runtime.h>

// Fused Poincare-ball: y = proj(expmap0(relu(logmap0(x))))
// 4 threads per row (D=64), 4 x float4 per thread.
// One warp covers 8 rows -> per-row scalar math amortized 4x vs 16-thr/row.

#define MIN_NORM  1e-7f
#define BALL_EPS  4e-3f
#define ATANH_EPS 1e-7f

__global__ __launch_bounds__(256)
void act_hyp_kernel(const float4* __restrict__ x,
                    const float* __restrict__ c,
                    float4* __restrict__ out,
                    int nrows)
{
    const int t    = blockIdx.x * blockDim.x + threadIdx.x;
    const int row  = t >> 2;
    if (row >= nrows) return;
    const int lane = t & 3;

    const float4* xp = x + (size_t)row * 16 + lane;

    // Load 4 float4 (64 B) of this row: quarters lane, lane+4, lane+8, lane+12
    float4 v[4];
    #pragma unroll
    for (int i = 0; i < 4; i++) v[i] = __ldcs(xp + i * 4);

    // relu'd copy + both squared sums in one pass
    float r[16];
    float s2  = 0.0f;
    float s2p = 0.0f;
    #pragma unroll
    for (int i = 0; i < 4; i++) {
        float a0 = v[i].x, a1 = v[i].y, a2 = v[i].z, a3 = v[i].w;
        s2 = fmaf(a0, a0, s2); s2 = fmaf(a1, a1, s2);
        s2 = fmaf(a2, a2, s2); s2 = fmaf(a3, a3, s2);
        float b0 = fmaxf(a0, 0.0f), b1 = fmaxf(a1, 0.0f);
        float b2 = fmaxf(a2, 0.0f), b3 = fmaxf(a3, 0.0f);
        s2p = fmaf(b0, b0, s2p); s2p = fmaf(b1, b1, s2p);
        s2p = fmaf(b2, b2, s2p); s2p = fmaf(b3, b3, s2p);
        r[i*4+0] = b0; r[i*4+1] = b1; r[i*4+2] = b2; r[i*4+3] = b3;
    }

    // 4-lane xor reduction (groups of 4 aligned within the warp)
    #pragma unroll
    for (int off = 2; off >= 1; off >>= 1) {
        s2  += __shfl_xor_sync(0xFFFFFFFFu, s2,  off);
        s2p += __shfl_xor_sync(0xFFFFFFFFu, s2p, off);
    }

    const float sqrt_c = sqrtf(c[0]);

    // logmap0 scale: f = atanh(min(sc*xn, 1-eps)) / (sc*xn)
    // atanh(a) = 0.5 * log((1+a)/(1-a)) via fast log (safe here: no cancellation)
    float xn  = fmaxf(sqrtf(s2), MIN_NORM);
    float sxn = sqrt_c * xn;
    float arg = fminf(sxn, 1.0f - ATANH_EPS);
    float ath = 0.5f * __logf(__fdividef(1.0f + arg, 1.0f - arg));
    float f   = __fdividef(ath, sxn);

    // expmap0 scale: t = tanh(sc*un)/(sc*un), un = f*||relu(x)|| (clamped)
    float un  = fmaxf(f * sqrtf(s2p), MIN_NORM);
    float sun = sqrt_c * un;
    float tt  = __fdividef(tanhf(sun), sun);

    // proj: ||y|| = un * tt analytically (both factors > 0)
    float yn      = fmaxf(un * tt, MIN_NORM);
    float maxnorm = __fdividef(1.0f - BALL_EPS, sqrt_c);
    float ps      = (yn > maxnorm) ? __fdividef(maxnorm, yn) : 1.0f;

    const float m = f * tt * ps;

    float4* op = out + (size_t)row * 16 + lane;
    #pragma unroll
    for (int i = 0; i < 4; i++) {
        float4 o;
        o.x = r[i*4+0] * m;
        o.y = r[i*4+1] * m;
        o.z = r[i*4+2] * m;
        o.w = r[i*4+3] * m;
        __stcs(op + i * 4, o);
    }
}

extern "C" void kernel_launch(void* const* d_in, const int* in_sizes, int n_in,
                              void* d_out, int out_size)
{
    const float4* x = (const float4*)d_in[0];
    const float*  c = (const float*)d_in[1];
    float4* out = (float4*)d_out;

    int nrows  = in_sizes[0] / 64;
    int blocks = (nrows + 63) / 64;   // 64 rows per 256-thread block
    act_hyp_kernel<<<blocks, 256>>>(x, c, out, nrows);
}